// round 10
// baseline (speedup 1.0000x reference)
#include <cuda_runtime.h>
#include <cuda_bf16.h>
#include <cstdint>

// Problem constants
#define Bsz 64
#define Tt  512
#define Ee  512
#define Hh  512
#define G4  2048          // 4*H
#define NC  64            // CTAs per direction in recurrence
#define AROW 520          // SMEM row stride (bf16): conflict-free for ldmatrix
#define ZST 34            // z SMEM row stride (floats)
#define REC_THREADS 256
#define REC_SMEM (192*AROW*2 + 64*ZST*4)
#define WSTRIDE ((size_t)G4*1024)   // per-weight split-buffer stride (elems)

// ---------------- scratch (static device memory; no allocation) ----------------
__device__ float g_xz0[(size_t)Bsz*Tt*G4];
__device__ float g_xz1[(size_t)Bsz*Tt*G4];
__device__ __nv_bfloat16 g_hh[2*2*Bsz*Hh];
__device__ __nv_bfloat16 g_hl[2*2*Bsz*Hh];
__device__ int   g_cnt[4];
__device__ __nv_bfloat16 g_ahi [(size_t)Bsz*Tt*1024];
__device__ __nv_bfloat16 g_alo [(size_t)Bsz*Tt*1024];
__device__ __nv_bfloat16 g_whiT[2*WSTRIDE];       // [2 weights][N=2048][K<=1024]
__device__ __nv_bfloat16 g_wloT[2*WSTRIDE];

__device__ __forceinline__ float sigm(float x) { return 1.0f / (1.0f + expf(-x)); }

__device__ __forceinline__ void cpasync16(uint32_t dst, const void* src) {
    asm volatile("cp.async.cg.shared.global [%0], [%1], 16;" :: "r"(dst), "l"(src));
}

#define LDSM4(r, addr)                                                         \
    asm volatile("ldmatrix.sync.aligned.m8n8.x4.shared.b16 {%0,%1,%2,%3}, [%4];" \
                 : "=r"((r)[0]), "=r"((r)[1]), "=r"((r)[2]), "=r"((r)[3])      \
                 : "r"(addr))

#define MMA16816(acc, a, b0, b1)                                               \
    asm volatile("mma.sync.aligned.m16n8k16.row.col.f32.bf16.bf16.f32 "        \
                 "{%0,%1,%2,%3}, {%4,%5,%6,%7}, {%8,%9}, {%0,%1,%2,%3};"       \
                 : "+f"((acc)[0]), "+f"((acc)[1]), "+f"((acc)[2]), "+f"((acc)[3]) \
                 : "r"((a)[0]), "r"((a)[1]), "r"((a)[2]), "r"((a)[3]),         \
                   "r"(b0), "r"(b1))

// ---------------- init ----------------
__global__ void k_init(int full) {
    int i = blockIdx.x * blockDim.x + threadIdx.x;
    uint4 z = make_uint4(0, 0, 0, 0);
    if (i < 16384) {
        ((uint4*)g_hh)[i] = z;
        ((uint4*)g_hl)[i] = z;
    }
    if (full && i < 4) g_cnt[i] = 0;
}

// ---------------- fused embedding gather + bf16 hi/lo split ----------------
__global__ void k_gatherSplit(const int* __restrict__ ids, const float* __restrict__ emb,
                              __nv_bfloat16* __restrict__ hi, __nv_bfloat16* __restrict__ lo) {
    int i = blockIdx.x * blockDim.x + threadIdx.x;
    int bt = i >> 7;
    int c  = i & 127;
    int id = __ldg(&ids[bt]);
    float4 v = __ldg((const float4*)emb + (size_t)id * 128 + c);
    __nv_bfloat16 h0 = __float2bfloat16(v.x), h1 = __float2bfloat16(v.y);
    __nv_bfloat16 h2 = __float2bfloat16(v.z), h3 = __float2bfloat16(v.w);
    __nv_bfloat16 l0 = __float2bfloat16(v.x - __bfloat162float(h0));
    __nv_bfloat16 l1 = __float2bfloat16(v.y - __bfloat162float(h1));
    __nv_bfloat16 l2 = __float2bfloat16(v.z - __bfloat162float(h2));
    __nv_bfloat16 l3 = __float2bfloat16(v.w - __bfloat162float(h3));
    ((__nv_bfloat162*)hi)[i*2]   = __nv_bfloat162(h0, h1);
    ((__nv_bfloat162*)hi)[i*2+1] = __nv_bfloat162(h2, h3);
    ((__nv_bfloat162*)lo)[i*2]   = __nv_bfloat162(l0, l1);
    ((__nv_bfloat162*)lo)[i*2+1] = __nv_bfloat162(l2, l3);
}

// ---------------- W split + transpose, both directions in one launch ----------------
__global__ void __launch_bounds__(256)
k_splitW2(const float* __restrict__ W0, const float* __restrict__ W1,
          __nv_bfloat16* __restrict__ hiT, __nv_bfloat16* __restrict__ loT, int K) {
    __shared__ float t[32][33];
    const float* W = blockIdx.z ? W1 : W0;
    __nv_bfloat16* hi = hiT + (size_t)blockIdx.z * WSTRIDE;
    __nv_bfloat16* lo = loT + (size_t)blockIdx.z * WSTRIDE;
    const int kb = blockIdx.y * 32, nb = blockIdx.x * 32;
    const int tx = threadIdx.x, ty = threadIdx.y;
#pragma unroll
    for (int r = ty; r < 32; r += 8)
        t[r][tx] = W[(size_t)(kb + r) * G4 + nb + tx];
    __syncthreads();
#pragma unroll
    for (int r = ty; r < 32; r += 8) {
        float v = t[tx][r];
        __nv_bfloat16 h = __float2bfloat16(v);
        __nv_bfloat16 l = __float2bfloat16(v - __bfloat162float(h));
        size_t o = (size_t)(nb + r) * K + kb + tx;
        hi[o] = h;
        lo[o] = l;
    }
}

// ---------------- tensor-core projection GEMM (ldmatrix + double buffer) ----------------
__global__ void __launch_bounds__(256)
k_hgemm(const __nv_bfloat16* __restrict__ Ahi, const __nv_bfloat16* __restrict__ Alo,
        const __nv_bfloat16* __restrict__ BhiT, const __nv_bfloat16* __restrict__ BloT,
        const float* __restrict__ bias, float* __restrict__ Y, int K) {
    const int N = 2048;
    __shared__ __nv_bfloat16 As[2][128 * 40];
    __shared__ __nv_bfloat16 Bs[2][128 * 40];

    const int tid = threadIdx.x;
    const int bm = blockIdx.y * 128, bn = blockIdx.x * 128;
    const int warp = tid >> 5, lane = tid & 31;
    const int mw = (warp & 1) * 64, nw = (warp >> 1) * 32;
    const int lr = lane >> 2, lc = (lane & 3) * 2;

    const int l_row = tid >> 2;
    const int l_q   = (tid & 3) * 8;

    float acc[4][4][4];
#pragma unroll
    for (int a = 0; a < 4; a++)
#pragma unroll
        for (int b = 0; b < 4; b++)
#pragma unroll
            for (int c = 0; c < 4; c++) acc[a][b][c] = 0.f;

    const int nk  = K >> 5;
    const int nch = 3 * nk;

    // ldmatrix lane offsets (validated pattern from k_rec, stride 40 bf16)
    const uint32_t aoffc = (uint32_t)(((mw + (lane & 15)) * 40 + ((lane >> 4) << 3)) * 2);
    const uint32_t boffc = (uint32_t)(((nw + (lane & 7)) * 40 + ((lane >> 3) << 3)) * 2);
    const uint32_t sAb[2] = {(uint32_t)__cvta_generic_to_shared(As[0]),
                             (uint32_t)__cvta_generic_to_shared(As[1])};
    const uint32_t sBb[2] = {(uint32_t)__cvta_generic_to_shared(Bs[0]),
                             (uint32_t)__cvta_generic_to_shared(Bs[1])};

    uint4 ra0 = *(const uint4*)(Ahi  + (size_t)(bm + l_row)      * K + l_q);
    uint4 ra1 = *(const uint4*)(Ahi  + (size_t)(bm + l_row + 64) * K + l_q);
    uint4 rb0 = *(const uint4*)(BhiT + (size_t)(bn + l_row)      * K + l_q);
    uint4 rb1 = *(const uint4*)(BhiT + (size_t)(bn + l_row + 64) * K + l_q);
    *(uint4*)&As[0][l_row * 40 + l_q]        = ra0;
    *(uint4*)&As[0][(l_row + 64) * 40 + l_q] = ra1;
    *(uint4*)&Bs[0][l_row * 40 + l_q]        = rb0;
    *(uint4*)&Bs[0][(l_row + 64) * 40 + l_q] = rb1;
    __syncthreads();

    for (int c = 0; c < nch; ++c) {
        const int cur = c & 1;
        if (c + 1 < nch) {
            const int c1 = c + 1;
            const int seg = c1 / nk;
            const int k0 = (c1 - seg * nk) * 32;
            const __nv_bfloat16* Ap = (seg == 2) ? Alo  : Ahi;
            const __nv_bfloat16* Bp = (seg == 1) ? BloT : BhiT;
            ra0 = *(const uint4*)(Ap + (size_t)(bm + l_row)      * K + k0 + l_q);
            ra1 = *(const uint4*)(Ap + (size_t)(bm + l_row + 64) * K + k0 + l_q);
            rb0 = *(const uint4*)(Bp + (size_t)(bn + l_row)      * K + k0 + l_q);
            rb1 = *(const uint4*)(Bp + (size_t)(bn + l_row + 64) * K + k0 + l_q);
        }

        // B fragments: one LDSM.x4 per n8 tile covers all 32 k
        uint32_t bfr[4][4];
        {
            const uint32_t bb = sBb[cur] + boffc;
#pragma unroll
            for (int nf = 0; nf < 4; nf++) LDSM4(bfr[nf], bb + (uint32_t)(nf * 8 * 40 * 2));
        }
        // two 16-k halves; A fragments reloaded per half
#pragma unroll
        for (int half = 0; half < 2; ++half) {
            uint32_t af[4][4];
            const uint32_t ab = sAb[cur] + aoffc + (uint32_t)(half * 32);
#pragma unroll
            for (int mf = 0; mf < 4; mf++) LDSM4(af[mf], ab + (uint32_t)(mf * 16 * 40 * 2));
#pragma unroll
            for (int mf = 0; mf < 4; mf++)
#pragma unroll
                for (int nf = 0; nf < 4; nf++)
                    MMA16816(acc[mf][nf], af[mf], bfr[nf][half * 2], bfr[nf][half * 2 + 1]);
        }

        if (c + 1 < nch) {
            const int nxt = cur ^ 1;
            *(uint4*)&As[nxt][l_row * 40 + l_q]        = ra0;
            *(uint4*)&As[nxt][(l_row + 64) * 40 + l_q] = ra1;
            *(uint4*)&Bs[nxt][l_row * 40 + l_q]        = rb0;
            *(uint4*)&Bs[nxt][(l_row + 64) * 40 + l_q] = rb1;
        }
        __syncthreads();
    }

#pragma unroll
    for (int nf = 0; nf < 4; nf++) {
        const int col = bn + nw + nf * 8 + lc;
        const float bz0 = __ldg(&bias[col]), bz1 = __ldg(&bias[col + 1]);
#pragma unroll
        for (int mf = 0; mf < 4; mf++) {
            const int row0 = bm + mw + mf * 16 + lr;
            float2 v0, v1;
            v0.x = acc[mf][nf][0] + bz0; v0.y = acc[mf][nf][1] + bz1;
            v1.x = acc[mf][nf][2] + bz0; v1.y = acc[mf][nf][3] + bz1;
            *(float2*)&Y[(size_t)row0 * N + col]       = v0;
            *(float2*)&Y[(size_t)(row0 + 8) * N + col] = v1;
        }
    }
}

// ---------------- persistent bidirectional LSTM recurrence (tensor-core) ----------------
__global__ void __launch_bounds__(REC_THREADS, 1)
k_rec(const float* __restrict__ xzf, const float* __restrict__ xzb,
      const float* __restrict__ Uf,  const float* __restrict__ Ub,
      float* __restrict__ hs_out, float* st_out,
      __nv_bfloat16* __restrict__ oh, __nv_bfloat16* __restrict__ ol, int layer) {
    extern __shared__ __nv_bfloat16 smb[];
    __nv_bfloat16* Ahi = smb;
    __nv_bfloat16* Alo = Ahi + 64 * AROW;
    __nv_bfloat16* Uhi = Alo + 64 * AROW;
    __nv_bfloat16* Ulo = Uhi + 32 * AROW;
    float* zf = (float*)(Ulo + 32 * AROW);

    const int dir = blockIdx.x >> 6;
    const int cid = blockIdx.x & 63;
    const float* xz = dir ? xzb : xzf;
    const float* U  = dir ? Ub  : Uf;
    int* cnt = &g_cnt[layer * 2 + dir];
    const int jbase = cid * 8;
    const int tid = threadIdx.x;
    const int lane = tid & 31, warp = tid >> 5;

    for (int idx = tid; idx < 512 * 32; idx += REC_THREADS) {
        int k = idx >> 5, n = idx & 31;
        float v = U[(size_t)k * G4 + (n >> 3) * Hh + jbase + (n & 7)];
        __nv_bfloat16 h = __float2bfloat16(v);
        Uhi[n * AROW + k] = h;
        Ulo[n * AROW + k] = __float2bfloat16(v - __bfloat162float(h));
    }

    const int eb = tid >> 2;
    const int eu = (tid & 3) * 2;
    float c0 = 0.f, c1 = 0.f;

    const int sr = tid >> 2, sq = tid & 3;

    const int mf  = warp & 3;
    const int nfg = warp >> 2;
    const int nb0 = nfg * 16;
    const uint32_t aoff  = (uint32_t)(((mf * 16 + (lane & 15)) * AROW + ((lane >> 4) << 3)) * 2);
    const uint32_t boff0 = (uint32_t)(((nb0 + (lane & 7)) * AROW + ((lane >> 3) << 3)) * 2);
    const uint32_t boff1 = boff0 + (uint32_t)(8 * AROW * 2);
    const uint32_t sAhi = (uint32_t)__cvta_generic_to_shared(Ahi);
    const uint32_t sAlo = (uint32_t)__cvta_generic_to_shared(Alo);
    const uint32_t sUhi = (uint32_t)__cvta_generic_to_shared(Uhi);
    const uint32_t sUlo = (uint32_t)__cvta_generic_to_shared(Ulo);

    const __nv_bfloat16* HHb = g_hh + (size_t)dir * 2 * Bsz * Hh;
    const __nv_bfloat16* HLb = g_hl + (size_t)dir * 2 * Bsz * Hh;

    __syncthreads();

    for (int s = 0; s < Tt; ++s) {
        const int tt = dir ? (Tt - 1 - s) : s;
        const int par = s & 1;
        const __nv_bfloat16* hpH = HHb + par * Bsz * Hh;
        const __nv_bfloat16* hpL = HLb + par * Bsz * Hh;
        __nv_bfloat16* hnH = (__nv_bfloat16*)HHb + (par ^ 1) * Bsz * Hh;
        __nv_bfloat16* hnL = (__nv_bfloat16*)HLb + (par ^ 1) * Bsz * Hh;

        const float* xzp = xz + ((size_t)eb * Tt + tt) * G4 + jbase;
        float x[8];
#pragma unroll
        for (int g = 0; g < 4; ++g) {
            x[g * 2]     = __ldcs(xzp + g * 512 + eu);
            x[g * 2 + 1] = __ldcs(xzp + g * 512 + eu + 1);
        }

        {
            const uint4* srcH = (const uint4*)(hpH + sr * 512);
            const uint4* srcL = (const uint4*)(hpL + sr * 512);
            const uint32_t dH = sAhi + (uint32_t)(sr * AROW * 2) + sq * 16;
            const uint32_t dL = sAlo + (uint32_t)(sr * AROW * 2) + sq * 16;
#pragma unroll
            for (int i = 0; i < 16; ++i) cpasync16(dH + i * 64, srcH + sq + 4 * i);
            asm volatile("cp.async.commit_group;");
#pragma unroll
            for (int i = 0; i < 16; ++i) cpasync16(dL + i * 64, srcL + sq + 4 * i);
            asm volatile("cp.async.commit_group;");
        }

        float a0c0[4] = {0.f,0.f,0.f,0.f}, a0c1[4] = {0.f,0.f,0.f,0.f};
        float a1c0[4] = {0.f,0.f,0.f,0.f}, a1c1[4] = {0.f,0.f,0.f,0.f};

        asm volatile("cp.async.wait_group 1;" ::: "memory");
        __syncthreads();
#pragma unroll
        for (int p = 0; p < 2; ++p) {
            const uint32_t ab  = sAhi + aoff;
            const uint32_t bb0 = (p == 1 ? sUlo : sUhi) + boff0;
            const uint32_t bb1 = (p == 1 ? sUlo : sUhi) + boff1;
#pragma unroll 4
            for (int kb = 0; kb < 16; ++kb) {
                const uint32_t ko = kb * 64;
                uint32_t a0[4], a1[4], b0[4], b1[4];
                LDSM4(a0, ab + ko);
                LDSM4(a1, ab + ko + 32);
                LDSM4(b0, bb0 + ko);
                LDSM4(b1, bb1 + ko);
                MMA16816(a0c0, a0, b0[0], b0[1]);
                MMA16816(a0c1, a0, b1[0], b1[1]);
                MMA16816(a1c0, a1, b0[2], b0[3]);
                MMA16816(a1c1, a1, b1[2], b1[3]);
            }
        }
        asm volatile("cp.async.wait_group 0;" ::: "memory");
        __syncthreads();
        {
            const uint32_t ab  = sAlo + aoff;
            const uint32_t bb0 = sUhi + boff0;
            const uint32_t bb1 = sUhi + boff1;
#pragma unroll 4
            for (int kb = 0; kb < 16; ++kb) {
                const uint32_t ko = kb * 64;
                uint32_t a0[4], a1[4], b0[4], b1[4];
                LDSM4(a0, ab + ko);
                LDSM4(a1, ab + ko + 32);
                LDSM4(b0, bb0 + ko);
                LDSM4(b1, bb1 + ko);
                MMA16816(a0c0, a0, b0[0], b0[1]);
                MMA16816(a0c1, a0, b1[0], b1[1]);
                MMA16816(a1c0, a1, b0[2], b0[3]);
                MMA16816(a1c1, a1, b1[2], b1[3]);
            }
        }

        {
            const int lr = lane >> 2, lc = (lane & 3) * 2;
            const int zr = mf * 16 + lr;
            *(float2*)&zf[zr * ZST + nb0 + lc] =
                make_float2(a0c0[0] + a1c0[0], a0c0[1] + a1c0[1]);
            *(float2*)&zf[(zr + 8) * ZST + nb0 + lc] =
                make_float2(a0c0[2] + a1c0[2], a0c0[3] + a1c0[3]);
            *(float2*)&zf[zr * ZST + nb0 + 8 + lc] =
                make_float2(a0c1[0] + a1c1[0], a0c1[1] + a1c1[1]);
            *(float2*)&zf[(zr + 8) * ZST + nb0 + 8 + lc] =
                make_float2(a0c1[2] + a1c1[2], a0c1[3] + a1c1[3]);
        }
        __syncthreads();

        float hv[2];
        __nv_bfloat16 hb[2], lb[2];
#pragma unroll
        for (int e = 0; e < 2; ++e) {
            const int u = eu + e;
            const float zi = zf[eb * ZST + u]      + x[0 + e];
            const float zF = zf[eb * ZST + 8 + u]  + x[2 + e];
            const float zg = zf[eb * ZST + 16 + u] + x[4 + e];
            const float zo = zf[eb * ZST + 24 + u] + x[6 + e];
            const float ig = sigm(zi), fg = sigm(zF);
            const float gg = tanhf(zg), og = sigm(zo);
            float& c = e ? c1 : c0;
            c = fg * c + ig * gg;
            hv[e] = og * tanhf(c);
            hb[e] = __float2bfloat16(hv[e]);
            lb[e] = __float2bfloat16(hv[e] - __bfloat162float(hb[e]));
            hnH[eb * Hh + jbase + u] = hb[e];
            hnL[eb * Hh + jbase + u] = lb[e];
        }

        // fence (drains only the 4 small h-state stores) + non-returning arrive
        __threadfence();
        __syncthreads();
        if (tid == 0)
            asm volatile("red.release.gpu.global.add.s32 [%0], 1;" :: "l"(cnt) : "memory");

        // bulk output stores in the barrier shadow
        const size_t ob = ((size_t)eb * Tt + tt) * 1024 + dir * Hh + jbase + eu;
        if (hs_out != nullptr) {
            hs_out[ob]     = hv[0];
            hs_out[ob + 1] = hv[1];
            if (st_out != nullptr && s == Tt - 1) {
#pragma unroll
                for (int e = 0; e < 2; ++e) {
                    st_out[eb * 1024 + dir * Hh + jbase + eu + e] = hv[e];
                    st_out[Bsz * 1024 + eb * 1024 + dir * Hh + jbase + eu + e] = e ? c1 : c0;
                }
            }
        } else {
            oh[ob] = hb[0]; oh[ob + 1] = hb[1];
            ol[ob] = lb[0]; ol[ob + 1] = lb[1];
        }

        if (tid == 0) {
            const int target = NC * (s + 1);
            int v;
            do {
                asm volatile("ld.acquire.gpu.global.s32 %0, [%1];"
                             : "=r"(v) : "l"(cnt) : "memory");
            } while (v < target);
        }
        __syncthreads();
    }
}

// ---------------- launch sequence ----------------
extern "C" void kernel_launch(void* const* d_in, const int* in_sizes, int n_in,
                              void* d_out, int out_size) {
    const int*   ids = (const int*)d_in[0];
    const float* emb = (const float*)d_in[1];
    const float *W1f = (const float*)d_in[2],  *U1f = (const float*)d_in[3],
                *b1f = (const float*)d_in[4];
    const float *W1b = (const float*)d_in[5],  *U1b = (const float*)d_in[6],
                *b1b = (const float*)d_in[7];
    const float *W2f = (const float*)d_in[8],  *U2f = (const float*)d_in[9],
                *b2f = (const float*)d_in[10];
    const float *W2b = (const float*)d_in[11], *U2b = (const float*)d_in[12],
                *b2b = (const float*)d_in[13];
    float* out = (float*)d_out;

    float *pxz0, *pxz1;
    __nv_bfloat16 *pahi, *palo, *pwhi, *pwlo;
    cudaGetSymbolAddress((void**)&pxz0, g_xz0);
    cudaGetSymbolAddress((void**)&pxz1, g_xz1);
    cudaGetSymbolAddress((void**)&pahi, g_ahi);
    cudaGetSymbolAddress((void**)&palo, g_alo);
    cudaGetSymbolAddress((void**)&pwhi, g_whiT);
    cudaGetSymbolAddress((void**)&pwlo, g_wloT);

    cudaFuncSetAttribute(k_rec, cudaFuncAttributeMaxDynamicSharedMemorySize, REC_SMEM);

    // launch indices: 0 init, 1 gatherSplit, 2 splitW2, 3 hgemm, 4 hgemm,
    //                 5 k_rec  <-- ncu -s 5 captures the recurrence
    k_init<<<128, 256>>>(1);
    k_gatherSplit<<<16384, 256>>>(ids, emb, pahi, palo);

    const dim3 gg(G4 / 128, (Bsz * Tt) / 128);
    const dim3 tw(32, 8);

    // ----- layer 1 (K = 512) -----
    {
        const int K = Ee;
        k_splitW2<<<dim3(G4 / 32, K / 32, 2), tw>>>(W1f, W1b, pwhi, pwlo, K);
        k_hgemm<<<gg, 256>>>(pahi, palo, pwhi, pwlo, b1f, pxz0, K);
        k_hgemm<<<gg, 256>>>(pahi, palo, pwhi + WSTRIDE, pwlo + WSTRIDE, b1b, pxz1, K);
    }
    k_rec<<<2 * NC, REC_THREADS, REC_SMEM>>>(pxz0, pxz1, U1f, U1b,
                                             nullptr, nullptr, pahi, palo, 0);
    k_init<<<128, 256>>>(0);

    // ----- layer 2 (K = 1024) -----
    {
        const int K = 2 * Hh;
        k_splitW2<<<dim3(G4 / 32, K / 32, 2), tw>>>(W2f, W2b, pwhi, pwlo, K);
        k_hgemm<<<gg, 256>>>(pahi, palo, pwhi, pwlo, b2f, pxz0, K);
        k_hgemm<<<gg, 256>>>(pahi, palo, pwhi + WSTRIDE, pwlo + WSTRIDE, b2b, pxz1, K);
    }
    k_rec<<<2 * NC, REC_THREADS, REC_SMEM>>>(pxz0, pxz1, U2f, U2b, out,
                                             out + (size_t)Bsz * Tt * 1024,
                                             nullptr, nullptr, 1);
}

// round 12
// speedup vs baseline: 1.0094x; 1.0094x over previous
#include <cuda_runtime.h>
#include <cuda_bf16.h>
#include <cstdint>

// Problem constants
#define Bsz 64
#define Tt  512
#define Ee  512
#define Hh  512
#define G4  2048          // 4*H
#define NC  64            // CTAs per direction in recurrence
#define AROW 520          // SMEM row stride (bf16): conflict-free for ldmatrix
#define ZST 34            // z SMEM row stride (floats)
#define REC_THREADS 512
#define REC_SMEM (192*AROW*2 + 64*ZST*4)
#define WSTRIDE ((size_t)G4*1024)   // per-weight split-buffer stride (elems)

// ---------------- scratch (static device memory; no allocation) ----------------
__device__ float g_xz0[(size_t)Bsz*Tt*G4];
__device__ float g_xz1[(size_t)Bsz*Tt*G4];
__device__ __nv_bfloat16 g_hh[2*2*Bsz*Hh];
__device__ __nv_bfloat16 g_hl[2*2*Bsz*Hh];
__device__ int   g_cnt[4];
__device__ __nv_bfloat16 g_ahi [(size_t)Bsz*Tt*1024];
__device__ __nv_bfloat16 g_alo [(size_t)Bsz*Tt*1024];
__device__ __nv_bfloat16 g_whiT[2*WSTRIDE];
__device__ __nv_bfloat16 g_wloT[2*WSTRIDE];

__device__ __forceinline__ float sigm(float x) { return 1.0f / (1.0f + expf(-x)); }

__device__ __forceinline__ void cpasync16(uint32_t dst, const void* src) {
    asm volatile("cp.async.cg.shared.global [%0], [%1], 16;" :: "r"(dst), "l"(src));
}

#define LDSM4(r, addr)                                                         \
    asm volatile("ldmatrix.sync.aligned.m8n8.x4.shared.b16 {%0,%1,%2,%3}, [%4];" \
                 : "=r"((r)[0]), "=r"((r)[1]), "=r"((r)[2]), "=r"((r)[3])      \
                 : "r"(addr))

#define MMA16816(acc, a, b0, b1)                                               \
    asm volatile("mma.sync.aligned.m16n8k16.row.col.f32.bf16.bf16.f32 "        \
                 "{%0,%1,%2,%3}, {%4,%5,%6,%7}, {%8,%9}, {%0,%1,%2,%3};"       \
                 : "+f"((acc)[0]), "+f"((acc)[1]), "+f"((acc)[2]), "+f"((acc)[3]) \
                 : "r"((a)[0]), "r"((a)[1]), "r"((a)[2]), "r"((a)[3]),         \
                   "r"(b0), "r"(b1))

// ---------------- init ----------------
__global__ void k_init(int full) {
    int i = blockIdx.x * blockDim.x + threadIdx.x;
    uint4 z = make_uint4(0, 0, 0, 0);
    if (i < 16384) {
        ((uint4*)g_hh)[i] = z;
        ((uint4*)g_hl)[i] = z;
    }
    if (full && i < 4) g_cnt[i] = 0;
}

// ---------------- fused embedding gather + bf16 hi/lo split ----------------
__global__ void k_gatherSplit(const int* __restrict__ ids, const float* __restrict__ emb,
                              __nv_bfloat16* __restrict__ hi, __nv_bfloat16* __restrict__ lo) {
    int i = blockIdx.x * blockDim.x + threadIdx.x;
    int bt = i >> 7;
    int c  = i & 127;
    int id = __ldg(&ids[bt]);
    float4 v = __ldg((const float4*)emb + (size_t)id * 128 + c);
    __nv_bfloat16 h0 = __float2bfloat16(v.x), h1 = __float2bfloat16(v.y);
    __nv_bfloat16 h2 = __float2bfloat16(v.z), h3 = __float2bfloat16(v.w);
    __nv_bfloat16 l0 = __float2bfloat16(v.x - __bfloat162float(h0));
    __nv_bfloat16 l1 = __float2bfloat16(v.y - __bfloat162float(h1));
    __nv_bfloat16 l2 = __float2bfloat16(v.z - __bfloat162float(h2));
    __nv_bfloat16 l3 = __float2bfloat16(v.w - __bfloat162float(h3));
    ((__nv_bfloat162*)hi)[i*2]   = __nv_bfloat162(h0, h1);
    ((__nv_bfloat162*)hi)[i*2+1] = __nv_bfloat162(h2, h3);
    ((__nv_bfloat162*)lo)[i*2]   = __nv_bfloat162(l0, l1);
    ((__nv_bfloat162*)lo)[i*2+1] = __nv_bfloat162(l2, l3);
}

// ---------------- W split + transpose, both directions in one launch ----------------
__global__ void __launch_bounds__(256)
k_splitW2(const float* __restrict__ W0, const float* __restrict__ W1,
          __nv_bfloat16* __restrict__ hiT, __nv_bfloat16* __restrict__ loT, int K) {
    __shared__ float t[32][33];
    const float* W = blockIdx.z ? W1 : W0;
    __nv_bfloat16* hi = hiT + (size_t)blockIdx.z * WSTRIDE;
    __nv_bfloat16* lo = loT + (size_t)blockIdx.z * WSTRIDE;
    const int kb = blockIdx.y * 32, nb = blockIdx.x * 32;
    const int tx = threadIdx.x, ty = threadIdx.y;
#pragma unroll
    for (int r = ty; r < 32; r += 8)
        t[r][tx] = W[(size_t)(kb + r) * G4 + nb + tx];
    __syncthreads();
#pragma unroll
    for (int r = ty; r < 32; r += 8) {
        float v = t[tx][r];
        __nv_bfloat16 h = __float2bfloat16(v);
        __nv_bfloat16 l = __float2bfloat16(v - __bfloat162float(h));
        size_t o = (size_t)(nb + r) * K + kb + tx;
        hi[o] = h;
        lo[o] = l;
    }
}

// ---------------- tensor-core projection GEMM (ldmatrix + double buffer) ----------------
__global__ void __launch_bounds__(256)
k_hgemm(const __nv_bfloat16* __restrict__ Ahi, const __nv_bfloat16* __restrict__ Alo,
        const __nv_bfloat16* __restrict__ BhiT, const __nv_bfloat16* __restrict__ BloT,
        const float* __restrict__ bias, float* __restrict__ Y, int K) {
    const int N = 2048;
    __shared__ __nv_bfloat16 As[2][128 * 40];
    __shared__ __nv_bfloat16 Bs[2][128 * 40];

    const int tid = threadIdx.x;
    const int bm = blockIdx.y * 128, bn = blockIdx.x * 128;
    const int warp = tid >> 5, lane = tid & 31;
    const int mw = (warp & 1) * 64, nw = (warp >> 1) * 32;
    const int lr = lane >> 2, lc = (lane & 3) * 2;

    const int l_row = tid >> 2;
    const int l_q   = (tid & 3) * 8;

    float acc[4][4][4];
#pragma unroll
    for (int a = 0; a < 4; a++)
#pragma unroll
        for (int b = 0; b < 4; b++)
#pragma unroll
            for (int c = 0; c < 4; c++) acc[a][b][c] = 0.f;

    const int nk  = K >> 5;
    const int nch = 3 * nk;

    const uint32_t aoffc = (uint32_t)(((mw + (lane & 15)) * 40 + ((lane >> 4) << 3)) * 2);
    const uint32_t boffc = (uint32_t)(((nw + (lane & 7)) * 40 + ((lane >> 3) << 3)) * 2);
    const uint32_t sAb[2] = {(uint32_t)__cvta_generic_to_shared(As[0]),
                             (uint32_t)__cvta_generic_to_shared(As[1])};
    const uint32_t sBb[2] = {(uint32_t)__cvta_generic_to_shared(Bs[0]),
                             (uint32_t)__cvta_generic_to_shared(Bs[1])};

    uint4 ra0 = *(const uint4*)(Ahi  + (size_t)(bm + l_row)      * K + l_q);
    uint4 ra1 = *(const uint4*)(Ahi  + (size_t)(bm + l_row + 64) * K + l_q);
    uint4 rb0 = *(const uint4*)(BhiT + (size_t)(bn + l_row)      * K + l_q);
    uint4 rb1 = *(const uint4*)(BhiT + (size_t)(bn + l_row + 64) * K + l_q);
    *(uint4*)&As[0][l_row * 40 + l_q]        = ra0;
    *(uint4*)&As[0][(l_row + 64) * 40 + l_q] = ra1;
    *(uint4*)&Bs[0][l_row * 40 + l_q]        = rb0;
    *(uint4*)&Bs[0][(l_row + 64) * 40 + l_q] = rb1;
    __syncthreads();

    for (int c = 0; c < nch; ++c) {
        const int cur = c & 1;
        if (c + 1 < nch) {
            const int c1 = c + 1;
            const int seg = c1 / nk;
            const int k0 = (c1 - seg * nk) * 32;
            const __nv_bfloat16* Ap = (seg == 2) ? Alo  : Ahi;
            const __nv_bfloat16* Bp = (seg == 1) ? BloT : BhiT;
            ra0 = *(const uint4*)(Ap + (size_t)(bm + l_row)      * K + k0 + l_q);
            ra1 = *(const uint4*)(Ap + (size_t)(bm + l_row + 64) * K + k0 + l_q);
            rb0 = *(const uint4*)(Bp + (size_t)(bn + l_row)      * K + k0 + l_q);
            rb1 = *(const uint4*)(Bp + (size_t)(bn + l_row + 64) * K + k0 + l_q);
        }

        uint32_t bfr[4][4];
        {
            const uint32_t bb = sBb[cur] + boffc;
#pragma unroll
            for (int nf = 0; nf < 4; nf++) LDSM4(bfr[nf], bb + (uint32_t)(nf * 8 * 40 * 2));
        }
#pragma unroll
        for (int half = 0; half < 2; ++half) {
            uint32_t af[4][4];
            const uint32_t ab = sAb[cur] + aoffc + (uint32_t)(half * 32);
#pragma unroll
            for (int mf = 0; mf < 4; mf++) LDSM4(af[mf], ab + (uint32_t)(mf * 16 * 40 * 2));
#pragma unroll
            for (int mf = 0; mf < 4; mf++)
#pragma unroll
                for (int nf = 0; nf < 4; nf++)
                    MMA16816(acc[mf][nf], af[mf], bfr[nf][half * 2], bfr[nf][half * 2 + 1]);
        }

        if (c + 1 < nch) {
            const int nxt = cur ^ 1;
            *(uint4*)&As[nxt][l_row * 40 + l_q]        = ra0;
            *(uint4*)&As[nxt][(l_row + 64) * 40 + l_q] = ra1;
            *(uint4*)&Bs[nxt][l_row * 40 + l_q]        = rb0;
            *(uint4*)&Bs[nxt][(l_row + 64) * 40 + l_q] = rb1;
        }
        __syncthreads();
    }

#pragma unroll
    for (int nf = 0; nf < 4; nf++) {
        const int col = bn + nw + nf * 8 + lc;
        const float bz0 = __ldg(&bias[col]), bz1 = __ldg(&bias[col + 1]);
#pragma unroll
        for (int mf = 0; mf < 4; mf++) {
            const int row0 = bm + mw + mf * 16 + lr;
            float2 v0, v1;
            v0.x = acc[mf][nf][0] + bz0; v0.y = acc[mf][nf][1] + bz1;
            v1.x = acc[mf][nf][2] + bz0; v1.y = acc[mf][nf][3] + bz1;
            *(float2*)&Y[(size_t)row0 * N + col]       = v0;
            *(float2*)&Y[(size_t)(row0 + 8) * N + col] = v1;
        }
    }
}

// ---------------- persistent bidirectional LSTM recurrence (tensor-core, 16 warps) ------
// 512 threads: warp tile 16m x 8n (mf = warp&3, nf = warp>>2).
// k loop: 16 iterations x 32 k (a0 at ko, a1 at ko+16k; B x4 tile covers the
// same 32 k) — identical coverage to the validated R6 pattern.
__global__ void __launch_bounds__(REC_THREADS, 1)
k_rec(const float* __restrict__ xzf, const float* __restrict__ xzb,
      const float* __restrict__ Uf,  const float* __restrict__ Ub,
      float* __restrict__ hs_out, float* st_out,
      __nv_bfloat16* __restrict__ oh, __nv_bfloat16* __restrict__ ol, int layer) {
    extern __shared__ __nv_bfloat16 smb[];
    __nv_bfloat16* Ahi = smb;                  // [64][AROW]
    __nv_bfloat16* Alo = Ahi + 64 * AROW;
    __nv_bfloat16* Uhi = Alo + 64 * AROW;      // [32][AROW]
    __nv_bfloat16* Ulo = Uhi + 32 * AROW;
    float* zf = (float*)(Ulo + 32 * AROW);     // [64][ZST]

    const int dir = blockIdx.x >> 6;
    const int cid = blockIdx.x & 63;
    const float* xz = dir ? xzb : xzf;
    const float* U  = dir ? Ub  : Uf;
    int* cnt = &g_cnt[layer * 2 + dir];
    const int jbase = cid * 8;
    const int tid = threadIdx.x;
    const int lane = tid & 31, warp = tid >> 5;

    // pack U slice -> bf16 hi/lo: Us[n = gate*8 + jj][k]
    for (int idx = tid; idx < 512 * 32; idx += REC_THREADS) {
        int k = idx >> 5, n = idx & 31;
        float v = U[(size_t)k * G4 + (n >> 3) * Hh + jbase + (n & 7)];
        __nv_bfloat16 h = __float2bfloat16(v);
        Uhi[n * AROW + k] = h;
        Ulo[n * AROW + k] = __float2bfloat16(v - __bfloat162float(h));
    }

    // epilogue mapping: thread -> (batch eb, unit u)
    const int eb = tid >> 3;          // 0..63
    const int u  = tid & 7;           // 0..7
    float cst = 0.f;

    // staging mapping: 8 threads per batch row, 8 uint4 each per buffer
    const int sr = tid >> 3, sq = tid & 7;

    // mma mapping: warp -> (m tile mf: rows mf*16..+15, n tile nf: cols nf*8..+7)
    const int mf = warp & 3;
    const int nf = warp >> 2;
    const uint32_t aoff = (uint32_t)(((mf * 16 + (lane & 15)) * AROW + ((lane >> 4) << 3)) * 2);
    const uint32_t boff = (uint32_t)(((nf * 8 + (lane & 7)) * AROW + ((lane >> 3) << 3)) * 2);
    const uint32_t sAhi = (uint32_t)__cvta_generic_to_shared(Ahi);
    const uint32_t sAlo = (uint32_t)__cvta_generic_to_shared(Alo);
    const uint32_t sUhi = (uint32_t)__cvta_generic_to_shared(Uhi);
    const uint32_t sUlo = (uint32_t)__cvta_generic_to_shared(Ulo);

    const __nv_bfloat16* HHb = g_hh + (size_t)dir * 2 * Bsz * Hh;
    const __nv_bfloat16* HLb = g_hl + (size_t)dir * 2 * Bsz * Hh;

    __syncthreads();

    for (int s = 0; s < Tt; ++s) {
        const int tt = dir ? (Tt - 1 - s) : s;
        const int par = s & 1;
        const __nv_bfloat16* hpH = HHb + par * Bsz * Hh;
        const __nv_bfloat16* hpL = HLb + par * Bsz * Hh;
        __nv_bfloat16* hnH = (__nv_bfloat16*)HHb + (par ^ 1) * Bsz * Hh;
        __nv_bfloat16* hnL = (__nv_bfloat16*)HLb + (par ^ 1) * Bsz * Hh;

        // prefetch xz gate pre-activations (1 unit/thread: 4 gates)
        const float* xzp = xz + ((size_t)eb * Tt + tt) * G4 + jbase + u;
        float x[4];
#pragma unroll
        for (int g = 0; g < 4; ++g) x[g] = __ldcs(xzp + g * 512);

        // stage h hi (group 0), then h lo (group 1)
        {
            const uint4* srcH = (const uint4*)(hpH + sr * 512);
            const uint4* srcL = (const uint4*)(hpL + sr * 512);
            const uint32_t dH = sAhi + (uint32_t)(sr * AROW * 2) + sq * 16;
            const uint32_t dL = sAlo + (uint32_t)(sr * AROW * 2) + sq * 16;
#pragma unroll
            for (int i = 0; i < 8; ++i) cpasync16(dH + i * 128, srcH + sq + 8 * i);
            asm volatile("cp.async.commit_group;");
#pragma unroll
            for (int i = 0; i < 8; ++i) cpasync16(dL + i * 128, srcL + sq + 8 * i);
            asm volatile("cp.async.commit_group;");
        }

        float acc[4] = {0.f, 0.f, 0.f, 0.f};

        // ---- wait hi group; run Ahi@Uhi and Ahi@Ulo while lo group flies ----
        asm volatile("cp.async.wait_group 1;" ::: "memory");
        __syncthreads();
#pragma unroll
        for (int p = 0; p < 2; ++p) {
            const uint32_t ab = sAhi + aoff;
            const uint32_t bb = (p == 1 ? sUlo : sUhi) + boff;
#pragma unroll 4
            for (int kb = 0; kb < 16; ++kb) {
                const uint32_t ko = kb * 64;       // 32 bf16 (= 32 k) per iteration
                uint32_t a0[4], a1[4], b0[4];
                LDSM4(a0, ab + ko);
                LDSM4(a1, ab + ko + 32);
                LDSM4(b0, bb + ko);
                MMA16816(acc, a0, b0[0], b0[1]);
                MMA16816(acc, a1, b0[2], b0[3]);
            }
        }
        // ---- wait lo group; run Alo@Uhi ----
        asm volatile("cp.async.wait_group 0;" ::: "memory");
        __syncthreads();
        {
            const uint32_t ab = sAlo + aoff;
            const uint32_t bb = sUhi + boff;
#pragma unroll 4
            for (int kb = 0; kb < 16; ++kb) {
                const uint32_t ko = kb * 64;
                uint32_t a0[4], a1[4], b0[4];
                LDSM4(a0, ab + ko);
                LDSM4(a1, ab + ko + 32);
                LDSM4(b0, bb + ko);
                MMA16816(acc, a0, b0[0], b0[1]);
                MMA16816(acc, a1, b0[2], b0[3]);
            }
        }

        // write z tile to SMEM: warp (mf,nf): rows mf*16+lr(+8), cols nf*8+lc..+1
        {
            const int lr = lane >> 2, lc = (lane & 3) * 2;
            *(float2*)&zf[(mf * 16 + lr) * ZST + nf * 8 + lc]     = make_float2(acc[0], acc[1]);
            *(float2*)&zf[(mf * 16 + lr + 8) * ZST + nf * 8 + lc] = make_float2(acc[2], acc[3]);
        }
        __syncthreads();

        // epilogue: 1 hidden unit per thread; write ONLY h-state before the fence
        const float zi = zf[eb * ZST + u]      + x[0];
        const float zF = zf[eb * ZST + 8 + u]  + x[1];
        const float zg = zf[eb * ZST + 16 + u] + x[2];
        const float zo = zf[eb * ZST + 24 + u] + x[3];
        const float ig = sigm(zi), fg = sigm(zF);
        const float gg = tanhf(zg), og = sigm(zo);
        cst = fg * cst + ig * gg;
        const float hv = og * tanhf(cst);
        const __nv_bfloat16 hb = __float2bfloat16(hv);
        const __nv_bfloat16 lb = __float2bfloat16(hv - __bfloat162float(hb));
        hnH[eb * Hh + jbase + u] = hb;
        hnL[eb * Hh + jbase + u] = lb;

        // fence (drains only the 2 small h-state stores) + arrive
        __threadfence();
        __syncthreads();
        if (tid == 0) atomicAdd(cnt, 1);

        // bulk output stores in the barrier shadow
        const size_t ob = ((size_t)eb * Tt + tt) * 1024 + dir * Hh + jbase + u;
        if (hs_out != nullptr) {
            hs_out[ob] = hv;
            if (st_out != nullptr && s == Tt - 1) {
                st_out[eb * 1024 + dir * Hh + jbase + u] = hv;
                st_out[Bsz * 1024 + eb * 1024 + dir * Hh + jbase + u] = cst;
            }
        } else {
            oh[ob] = hb;
            ol[ob] = lb;
        }

        // spin for all CTAs of this direction
        if (tid == 0) {
            const int target = NC * (s + 1);
            int v;
            do {
                asm volatile("ld.acquire.gpu.global.s32 %0, [%1];"
                             : "=r"(v) : "l"(cnt) : "memory");
            } while (v < target);
        }
        __syncthreads();
    }
}

// ---------------- launch sequence ----------------
extern "C" void kernel_launch(void* const* d_in, const int* in_sizes, int n_in,
                              void* d_out, int out_size) {
    const int*   ids = (const int*)d_in[0];
    const float* emb = (const float*)d_in[1];
    const float *W1f = (const float*)d_in[2],  *U1f = (const float*)d_in[3],
                *b1f = (const float*)d_in[4];
    const float *W1b = (const float*)d_in[5],  *U1b = (const float*)d_in[6],
                *b1b = (const float*)d_in[7];
    const float *W2f = (const float*)d_in[8],  *U2f = (const float*)d_in[9],
                *b2f = (const float*)d_in[10];
    const float *W2b = (const float*)d_in[11], *U2b = (const float*)d_in[12],
                *b2b = (const float*)d_in[13];
    float* out = (float*)d_out;

    float *pxz0, *pxz1;
    __nv_bfloat16 *pahi, *palo, *pwhi, *pwlo;
    cudaGetSymbolAddress((void**)&pxz0, g_xz0);
    cudaGetSymbolAddress((void**)&pxz1, g_xz1);
    cudaGetSymbolAddress((void**)&pahi, g_ahi);
    cudaGetSymbolAddress((void**)&palo, g_alo);
    cudaGetSymbolAddress((void**)&pwhi, g_whiT);
    cudaGetSymbolAddress((void**)&pwlo, g_wloT);

    cudaFuncSetAttribute(k_rec, cudaFuncAttributeMaxDynamicSharedMemorySize, REC_SMEM);

    k_init<<<128, 256>>>(1);
    k_gatherSplit<<<16384, 256>>>(ids, emb, pahi, palo);

    const dim3 gg(G4 / 128, (Bsz * Tt) / 128);
    const dim3 tw(32, 8);

    // ----- layer 1 (K = 512) -----
    {
        const int K = Ee;
        k_splitW2<<<dim3(G4 / 32, K / 32, 2), tw>>>(W1f, W1b, pwhi, pwlo, K);
        k_hgemm<<<gg, 256>>>(pahi, palo, pwhi, pwlo, b1f, pxz0, K);
        k_hgemm<<<gg, 256>>>(pahi, palo, pwhi + WSTRIDE, pwlo + WSTRIDE, b1b, pxz1, K);
    }
    k_rec<<<2 * NC, REC_THREADS, REC_SMEM>>>(pxz0, pxz1, U1f, U1b,
                                             nullptr, nullptr, pahi, palo, 0);
    k_init<<<128, 256>>>(0);

    // ----- layer 2 (K = 1024) -----
    {
        const int K = 2 * Hh;
        k_splitW2<<<dim3(G4 / 32, K / 32, 2), tw>>>(W2f, W2b, pwhi, pwlo, K);
        k_hgemm<<<gg, 256>>>(pahi, palo, pwhi, pwlo, b2f, pxz0, K);
        k_hgemm<<<gg, 256>>>(pahi, palo, pwhi + WSTRIDE, pwlo + WSTRIDE, b2b, pxz1, K);
    }
    k_rec<<<2 * NC, REC_THREADS, REC_SMEM>>>(pxz0, pxz1, U2f, U2b, out,
                                             out + (size_t)Bsz * Tt * 1024,
                                             nullptr, nullptr, 1);
}

// round 13
// speedup vs baseline: 1.0898x; 1.0796x over previous
#include <cuda_runtime.h>
#include <cuda_bf16.h>
#include <cstdint>

// Problem constants
#define Bsz 64
#define Tt  512
#define Ee  512
#define Hh  512
#define G4  2048          // 4*H
#define NC  64            // CTAs per direction in recurrence
#define AROW 520          // SMEM row stride (bf16): conflict-free for ldmatrix
#define ZST 34            // z SMEM row stride (floats)
#define REC_THREADS 256
#define REC_SMEM (192*AROW*2 + 64*ZST*4)
#define WSTRIDE ((size_t)G4*1024)   // per-weight split-buffer stride (elems)

// ---------------- scratch (static device memory; no allocation) ----------------
__device__ float g_xz0[(size_t)Bsz*Tt*G4];
__device__ float g_xz1[(size_t)Bsz*Tt*G4];
__device__ __nv_bfloat16 g_hh[2*2*Bsz*Hh];
__device__ __nv_bfloat16 g_hl[2*2*Bsz*Hh];
__device__ int   g_cnt[4];
__device__ __nv_bfloat16 g_ahi [(size_t)Bsz*Tt*1024];
__device__ __nv_bfloat16 g_alo [(size_t)Bsz*Tt*1024];
__device__ __nv_bfloat16 g_whiT[2*WSTRIDE];
__device__ __nv_bfloat16 g_wloT[2*WSTRIDE];

__device__ __forceinline__ float sigm(float x) { return 1.0f / (1.0f + expf(-x)); }

__device__ __forceinline__ void cpasync16(uint32_t dst, const void* src) {
    asm volatile("cp.async.cg.shared.global [%0], [%1], 16;" :: "r"(dst), "l"(src));
}

#define LDSM4(r, addr)                                                         \
    asm volatile("ldmatrix.sync.aligned.m8n8.x4.shared.b16 {%0,%1,%2,%3}, [%4];" \
                 : "=r"((r)[0]), "=r"((r)[1]), "=r"((r)[2]), "=r"((r)[3])      \
                 : "r"(addr))

#define MMA16816(acc, a, b0, b1)                                               \
    asm volatile("mma.sync.aligned.m16n8k16.row.col.f32.bf16.bf16.f32 "        \
                 "{%0,%1,%2,%3}, {%4,%5,%6,%7}, {%8,%9}, {%0,%1,%2,%3};"       \
                 : "+f"((acc)[0]), "+f"((acc)[1]), "+f"((acc)[2]), "+f"((acc)[3]) \
                 : "r"((a)[0]), "r"((a)[1]), "r"((a)[2]), "r"((a)[3]),         \
                   "r"(b0), "r"(b1))

// ---------------- init ----------------
__global__ void k_init(int full) {
    int i = blockIdx.x * blockDim.x + threadIdx.x;
    uint4 z = make_uint4(0, 0, 0, 0);
    if (i < 16384) {
        ((uint4*)g_hh)[i] = z;
        ((uint4*)g_hl)[i] = z;
    }
    if (full && i < 4) g_cnt[i] = 0;
}

// ---------------- fused embedding gather + bf16 hi/lo split ----------------
__global__ void k_gatherSplit(const int* __restrict__ ids, const float* __restrict__ emb,
                              __nv_bfloat16* __restrict__ hi, __nv_bfloat16* __restrict__ lo) {
    int i = blockIdx.x * blockDim.x + threadIdx.x;
    int bt = i >> 7;
    int c  = i & 127;
    int id = __ldg(&ids[bt]);
    float4 v = __ldg((const float4*)emb + (size_t)id * 128 + c);
    __nv_bfloat16 h0 = __float2bfloat16(v.x), h1 = __float2bfloat16(v.y);
    __nv_bfloat16 h2 = __float2bfloat16(v.z), h3 = __float2bfloat16(v.w);
    __nv_bfloat16 l0 = __float2bfloat16(v.x - __bfloat162float(h0));
    __nv_bfloat16 l1 = __float2bfloat16(v.y - __bfloat162float(h1));
    __nv_bfloat16 l2 = __float2bfloat16(v.z - __bfloat162float(h2));
    __nv_bfloat16 l3 = __float2bfloat16(v.w - __bfloat162float(h3));
    ((__nv_bfloat162*)hi)[i*2]   = __nv_bfloat162(h0, h1);
    ((__nv_bfloat162*)hi)[i*2+1] = __nv_bfloat162(h2, h3);
    ((__nv_bfloat162*)lo)[i*2]   = __nv_bfloat162(l0, l1);
    ((__nv_bfloat162*)lo)[i*2+1] = __nv_bfloat162(l2, l3);
}

// ---------------- W split + transpose, both directions in one launch ----------------
__global__ void __launch_bounds__(256)
k_splitW2(const float* __restrict__ W0, const float* __restrict__ W1,
          __nv_bfloat16* __restrict__ hiT, __nv_bfloat16* __restrict__ loT, int K) {
    __shared__ float t[32][33];
    const float* W = blockIdx.z ? W1 : W0;
    __nv_bfloat16* hi = hiT + (size_t)blockIdx.z * WSTRIDE;
    __nv_bfloat16* lo = loT + (size_t)blockIdx.z * WSTRIDE;
    const int kb = blockIdx.y * 32, nb = blockIdx.x * 32;
    const int tx = threadIdx.x, ty = threadIdx.y;
#pragma unroll
    for (int r = ty; r < 32; r += 8)
        t[r][tx] = W[(size_t)(kb + r) * G4 + nb + tx];
    __syncthreads();
#pragma unroll
    for (int r = ty; r < 32; r += 8) {
        float v = t[tx][r];
        __nv_bfloat16 h = __float2bfloat16(v);
        __nv_bfloat16 l = __float2bfloat16(v - __bfloat162float(h));
        size_t o = (size_t)(nb + r) * K + kb + tx;
        hi[o] = h;
        lo[o] = l;
    }
}

// ---------------- tensor-core projection GEMM (ldmatrix + 3-stage cp.async) ----------------
__global__ void __launch_bounds__(256)
k_hgemm(const __nv_bfloat16* __restrict__ Ahi, const __nv_bfloat16* __restrict__ Alo,
        const __nv_bfloat16* __restrict__ BhiT, const __nv_bfloat16* __restrict__ BloT,
        const float* __restrict__ bias, float* __restrict__ Y, int K) {
    const int N = 2048;
    __shared__ __nv_bfloat16 As[3][128 * 40];
    __shared__ __nv_bfloat16 Bs[3][128 * 40];

    const int tid = threadIdx.x;
    const int bm = blockIdx.y * 128, bn = blockIdx.x * 128;
    const int warp = tid >> 5, lane = tid & 31;
    const int mw = (warp & 1) * 64, nw = (warp >> 1) * 32;
    const int lr = lane >> 2, lc = (lane & 3) * 2;

    const int l_row = tid >> 2;            // 0..63 (+64 second half)
    const int l_q   = (tid & 3) * 8;       // bf16 col offset

    float acc[4][4][4];
#pragma unroll
    for (int a = 0; a < 4; a++)
#pragma unroll
        for (int b = 0; b < 4; b++)
#pragma unroll
            for (int c = 0; c < 4; c++) acc[a][b][c] = 0.f;

    const int nk  = K >> 5;
    const int nch = 3 * nk;

    const uint32_t aoffc = (uint32_t)(((mw + (lane & 15)) * 40 + ((lane >> 4) << 3)) * 2);
    const uint32_t boffc = (uint32_t)(((nw + (lane & 7)) * 40 + ((lane >> 3) << 3)) * 2);
    const uint32_t sAb[3] = {(uint32_t)__cvta_generic_to_shared(As[0]),
                             (uint32_t)__cvta_generic_to_shared(As[1]),
                             (uint32_t)__cvta_generic_to_shared(As[2])};
    const uint32_t sBb[3] = {(uint32_t)__cvta_generic_to_shared(Bs[0]),
                             (uint32_t)__cvta_generic_to_shared(Bs[1]),
                             (uint32_t)__cvta_generic_to_shared(Bs[2])};
    const uint32_t ldst = (uint32_t)((l_row * 40 + l_q) * 2);     // thread's smem slot
    const uint32_t ldst2 = ldst + (uint32_t)(64 * 40 * 2);        // second-half row

    // issue cp.async group for chunk c into stage c%3
    auto issue = [&](int c) {
        const int seg = c / nk;
        const int k0 = (c - seg * nk) * 32;
        const __nv_bfloat16* Ap = (seg == 2) ? Alo  : Ahi;
        const __nv_bfloat16* Bp = (seg == 1) ? BloT : BhiT;
        const int st = c % 3;
        cpasync16(sAb[st] + ldst,  Ap + (size_t)(bm + l_row)      * K + k0 + l_q);
        cpasync16(sAb[st] + ldst2, Ap + (size_t)(bm + l_row + 64) * K + k0 + l_q);
        cpasync16(sBb[st] + ldst,  Bp + (size_t)(bn + l_row)      * K + k0 + l_q);
        cpasync16(sBb[st] + ldst2, Bp + (size_t)(bn + l_row + 64) * K + k0 + l_q);
        asm volatile("cp.async.commit_group;");
    };

    issue(0);
    issue(1);

    for (int c = 0; c < nch; ++c) {
        if (c + 1 < nch) asm volatile("cp.async.wait_group 1;" ::: "memory");
        else             asm volatile("cp.async.wait_group 0;" ::: "memory");
        __syncthreads();
        if (c + 2 < nch) issue(c + 2);

        const int st = c % 3;
        uint32_t bfr[4][4];
        {
            const uint32_t bb = sBb[st] + boffc;
#pragma unroll
            for (int nf = 0; nf < 4; nf++) LDSM4(bfr[nf], bb + (uint32_t)(nf * 8 * 40 * 2));
        }
#pragma unroll
        for (int half = 0; half < 2; ++half) {
            uint32_t af[4][4];
            const uint32_t ab = sAb[st] + aoffc + (uint32_t)(half * 32);
#pragma unroll
            for (int mf = 0; mf < 4; mf++) LDSM4(af[mf], ab + (uint32_t)(mf * 16 * 40 * 2));
#pragma unroll
            for (int mf = 0; mf < 4; mf++)
#pragma unroll
                for (int nf = 0; nf < 4; nf++)
                    MMA16816(acc[mf][nf], af[mf], bfr[nf][half * 2], bfr[nf][half * 2 + 1]);
        }
        __syncthreads();
    }

#pragma unroll
    for (int nf = 0; nf < 4; nf++) {
        const int col = bn + nw + nf * 8 + lc;
        const float bz0 = __ldg(&bias[col]), bz1 = __ldg(&bias[col + 1]);
#pragma unroll
        for (int mf = 0; mf < 4; mf++) {
            const int row0 = bm + mw + mf * 16 + lr;
            float2 v0, v1;
            v0.x = acc[mf][nf][0] + bz0; v0.y = acc[mf][nf][1] + bz1;
            v1.x = acc[mf][nf][2] + bz0; v1.y = acc[mf][nf][3] + bz1;
            *(float2*)&Y[(size_t)row0 * N + col]       = v0;
            *(float2*)&Y[(size_t)(row0 + 8) * N + col] = v1;
        }
    }
}

// ---------------- persistent bidirectional LSTM recurrence (R8 winner, verbatim) --------
__global__ void __launch_bounds__(REC_THREADS, 1)
k_rec(const float* __restrict__ xzf, const float* __restrict__ xzb,
      const float* __restrict__ Uf,  const float* __restrict__ Ub,
      float* __restrict__ hs_out, float* st_out,
      __nv_bfloat16* __restrict__ oh, __nv_bfloat16* __restrict__ ol, int layer) {
    extern __shared__ __nv_bfloat16 smb[];
    __nv_bfloat16* Ahi = smb;                  // [64][AROW]
    __nv_bfloat16* Alo = Ahi + 64 * AROW;
    __nv_bfloat16* Uhi = Alo + 64 * AROW;      // [32][AROW]
    __nv_bfloat16* Ulo = Uhi + 32 * AROW;
    float* zf = (float*)(Ulo + 32 * AROW);     // [64][ZST]

    const int dir = blockIdx.x >> 6;
    const int cid = blockIdx.x & 63;
    const float* xz = dir ? xzb : xzf;
    const float* U  = dir ? Ub  : Uf;
    int* cnt = &g_cnt[layer * 2 + dir];
    const int jbase = cid * 8;
    const int tid = threadIdx.x;
    const int lane = tid & 31, warp = tid >> 5;

    for (int idx = tid; idx < 512 * 32; idx += REC_THREADS) {
        int k = idx >> 5, n = idx & 31;
        float v = U[(size_t)k * G4 + (n >> 3) * Hh + jbase + (n & 7)];
        __nv_bfloat16 h = __float2bfloat16(v);
        Uhi[n * AROW + k] = h;
        Ulo[n * AROW + k] = __float2bfloat16(v - __bfloat162float(h));
    }

    const int eb = tid >> 2;
    const int eu = (tid & 3) * 2;
    float c0 = 0.f, c1 = 0.f;

    const int sr = tid >> 2, sq = tid & 3;

    const int mf  = warp & 3;
    const int nfg = warp >> 2;
    const int nb0 = nfg * 16;
    const uint32_t aoff  = (uint32_t)(((mf * 16 + (lane & 15)) * AROW + ((lane >> 4) << 3)) * 2);
    const uint32_t boff0 = (uint32_t)(((nb0 + (lane & 7)) * AROW + ((lane >> 3) << 3)) * 2);
    const uint32_t boff1 = boff0 + (uint32_t)(8 * AROW * 2);
    const uint32_t sAhi = (uint32_t)__cvta_generic_to_shared(Ahi);
    const uint32_t sAlo = (uint32_t)__cvta_generic_to_shared(Alo);
    const uint32_t sUhi = (uint32_t)__cvta_generic_to_shared(Uhi);
    const uint32_t sUlo = (uint32_t)__cvta_generic_to_shared(Ulo);

    const __nv_bfloat16* HHb = g_hh + (size_t)dir * 2 * Bsz * Hh;
    const __nv_bfloat16* HLb = g_hl + (size_t)dir * 2 * Bsz * Hh;

    __syncthreads();

    for (int s = 0; s < Tt; ++s) {
        const int tt = dir ? (Tt - 1 - s) : s;
        const int par = s & 1;
        const __nv_bfloat16* hpH = HHb + par * Bsz * Hh;
        const __nv_bfloat16* hpL = HLb + par * Bsz * Hh;
        __nv_bfloat16* hnH = (__nv_bfloat16*)HHb + (par ^ 1) * Bsz * Hh;
        __nv_bfloat16* hnL = (__nv_bfloat16*)HLb + (par ^ 1) * Bsz * Hh;

        const float* xzp = xz + ((size_t)eb * Tt + tt) * G4 + jbase;
        float x[8];
#pragma unroll
        for (int g = 0; g < 4; ++g) {
            x[g * 2]     = __ldcs(xzp + g * 512 + eu);
            x[g * 2 + 1] = __ldcs(xzp + g * 512 + eu + 1);
        }

        {
            const uint4* srcH = (const uint4*)(hpH + sr * 512);
            const uint4* srcL = (const uint4*)(hpL + sr * 512);
            const uint32_t dH = sAhi + (uint32_t)(sr * AROW * 2) + sq * 16;
            const uint32_t dL = sAlo + (uint32_t)(sr * AROW * 2) + sq * 16;
#pragma unroll
            for (int i = 0; i < 16; ++i) cpasync16(dH + i * 64, srcH + sq + 4 * i);
            asm volatile("cp.async.commit_group;");
#pragma unroll
            for (int i = 0; i < 16; ++i) cpasync16(dL + i * 64, srcL + sq + 4 * i);
            asm volatile("cp.async.commit_group;");
        }

        float a0c0[4] = {0.f,0.f,0.f,0.f}, a0c1[4] = {0.f,0.f,0.f,0.f};
        float a1c0[4] = {0.f,0.f,0.f,0.f}, a1c1[4] = {0.f,0.f,0.f,0.f};

        asm volatile("cp.async.wait_group 1;" ::: "memory");
        __syncthreads();
#pragma unroll
        for (int p = 0; p < 2; ++p) {
            const uint32_t ab  = sAhi + aoff;
            const uint32_t bb0 = (p == 1 ? sUlo : sUhi) + boff0;
            const uint32_t bb1 = (p == 1 ? sUlo : sUhi) + boff1;
#pragma unroll 4
            for (int kb = 0; kb < 16; ++kb) {
                const uint32_t ko = kb * 64;
                uint32_t a0[4], a1[4], b0[4], b1[4];
                LDSM4(a0, ab + ko);
                LDSM4(a1, ab + ko + 32);
                LDSM4(b0, bb0 + ko);
                LDSM4(b1, bb1 + ko);
                MMA16816(a0c0, a0, b0[0], b0[1]);
                MMA16816(a0c1, a0, b1[0], b1[1]);
                MMA16816(a1c0, a1, b0[2], b0[3]);
                MMA16816(a1c1, a1, b1[2], b1[3]);
            }
        }
        asm volatile("cp.async.wait_group 0;" ::: "memory");
        __syncthreads();
        {
            const uint32_t ab  = sAlo + aoff;
            const uint32_t bb0 = sUhi + boff0;
            const uint32_t bb1 = sUhi + boff1;
#pragma unroll 4
            for (int kb = 0; kb < 16; ++kb) {
                const uint32_t ko = kb * 64;
                uint32_t a0[4], a1[4], b0[4], b1[4];
                LDSM4(a0, ab + ko);
                LDSM4(a1, ab + ko + 32);
                LDSM4(b0, bb0 + ko);
                LDSM4(b1, bb1 + ko);
                MMA16816(a0c0, a0, b0[0], b0[1]);
                MMA16816(a0c1, a0, b1[0], b1[1]);
                MMA16816(a1c0, a1, b0[2], b0[3]);
                MMA16816(a1c1, a1, b1[2], b1[3]);
            }
        }

        {
            const int lr = lane >> 2, lc = (lane & 3) * 2;
            const int zr = mf * 16 + lr;
            *(float2*)&zf[zr * ZST + nb0 + lc] =
                make_float2(a0c0[0] + a1c0[0], a0c0[1] + a1c0[1]);
            *(float2*)&zf[(zr + 8) * ZST + nb0 + lc] =
                make_float2(a0c0[2] + a1c0[2], a0c0[3] + a1c0[3]);
            *(float2*)&zf[zr * ZST + nb0 + 8 + lc] =
                make_float2(a0c1[0] + a1c1[0], a0c1[1] + a1c1[1]);
            *(float2*)&zf[(zr + 8) * ZST + nb0 + 8 + lc] =
                make_float2(a0c1[2] + a1c1[2], a0c1[3] + a1c1[3]);
        }
        __syncthreads();

        float hv[2];
        __nv_bfloat16 hb[2], lb[2];
#pragma unroll
        for (int e = 0; e < 2; ++e) {
            const int u = eu + e;
            const float zi = zf[eb * ZST + u]      + x[0 + e];
            const float zF = zf[eb * ZST + 8 + u]  + x[2 + e];
            const float zg = zf[eb * ZST + 16 + u] + x[4 + e];
            const float zo = zf[eb * ZST + 24 + u] + x[6 + e];
            const float ig = sigm(zi), fg = sigm(zF);
            const float gg = tanhf(zg), og = sigm(zo);
            float& c = e ? c1 : c0;
            c = fg * c + ig * gg;
            hv[e] = og * tanhf(c);
            hb[e] = __float2bfloat16(hv[e]);
            lb[e] = __float2bfloat16(hv[e] - __bfloat162float(hb[e]));
            hnH[eb * Hh + jbase + u] = hb[e];
            hnL[eb * Hh + jbase + u] = lb[e];
        }

        __threadfence();
        __syncthreads();
        if (tid == 0) atomicAdd(cnt, 1);

        const size_t ob = ((size_t)eb * Tt + tt) * 1024 + dir * Hh + jbase + eu;
        if (hs_out != nullptr) {
            hs_out[ob]     = hv[0];
            hs_out[ob + 1] = hv[1];
            if (st_out != nullptr && s == Tt - 1) {
#pragma unroll
                for (int e = 0; e < 2; ++e) {
                    st_out[eb * 1024 + dir * Hh + jbase + eu + e] = hv[e];
                    st_out[Bsz * 1024 + eb * 1024 + dir * Hh + jbase + eu + e] = e ? c1 : c0;
                }
            }
        } else {
            oh[ob] = hb[0]; oh[ob + 1] = hb[1];
            ol[ob] = lb[0]; ol[ob + 1] = lb[1];
        }

        if (tid == 0) {
            const int target = NC * (s + 1);
            int v;
            do {
                asm volatile("ld.acquire.gpu.global.s32 %0, [%1];"
                             : "=r"(v) : "l"(cnt) : "memory");
            } while (v < target);
        }
        __syncthreads();
    }
}

// ---------------- launch sequence ----------------
extern "C" void kernel_launch(void* const* d_in, const int* in_sizes, int n_in,
                              void* d_out, int out_size) {
    const int*   ids = (const int*)d_in[0];
    const float* emb = (const float*)d_in[1];
    const float *W1f = (const float*)d_in[2],  *U1f = (const float*)d_in[3],
                *b1f = (const float*)d_in[4];
    const float *W1b = (const float*)d_in[5],  *U1b = (const float*)d_in[6],
                *b1b = (const float*)d_in[7];
    const float *W2f = (const float*)d_in[8],  *U2f = (const float*)d_in[9],
                *b2f = (const float*)d_in[10];
    const float *W2b = (const float*)d_in[11], *U2b = (const float*)d_in[12],
                *b2b = (const float*)d_in[13];
    float* out = (float*)d_out;

    float *pxz0, *pxz1;
    __nv_bfloat16 *pahi, *palo, *pwhi, *pwlo;
    cudaGetSymbolAddress((void**)&pxz0, g_xz0);
    cudaGetSymbolAddress((void**)&pxz1, g_xz1);
    cudaGetSymbolAddress((void**)&pahi, g_ahi);
    cudaGetSymbolAddress((void**)&palo, g_alo);
    cudaGetSymbolAddress((void**)&pwhi, g_whiT);
    cudaGetSymbolAddress((void**)&pwlo, g_wloT);

    cudaFuncSetAttribute(k_rec, cudaFuncAttributeMaxDynamicSharedMemorySize, REC_SMEM);

    k_init<<<128, 256>>>(1);
    k_gatherSplit<<<16384, 256>>>(ids, emb, pahi, palo);

    const dim3 gg(G4 / 128, (Bsz * Tt) / 128);
    const dim3 tw(32, 8);

    // ----- layer 1 (K = 512) -----
    {
        const int K = Ee;
        k_splitW2<<<dim3(G4 / 32, K / 32, 2), tw>>>(W1f, W1b, pwhi, pwlo, K);
        k_hgemm<<<gg, 256>>>(pahi, palo, pwhi, pwlo, b1f, pxz0, K);
        k_hgemm<<<gg, 256>>>(pahi, palo, pwhi + WSTRIDE, pwlo + WSTRIDE, b1b, pxz1, K);
    }
    k_rec<<<2 * NC, REC_THREADS, REC_SMEM>>>(pxz0, pxz1, U1f, U1b,
                                             nullptr, nullptr, pahi, palo, 0);
    k_init<<<128, 256>>>(0);

    // ----- layer 2 (K = 1024) -----
    {
        const int K = 2 * Hh;
        k_splitW2<<<dim3(G4 / 32, K / 32, 2), tw>>>(W2f, W2b, pwhi, pwlo, K);
        k_hgemm<<<gg, 256>>>(pahi, palo, pwhi, pwlo, b2f, pxz0, K);
        k_hgemm<<<gg, 256>>>(pahi, palo, pwhi + WSTRIDE, pwlo + WSTRIDE, b2b, pxz1, K);
    }
    k_rec<<<2 * NC, REC_THREADS, REC_SMEM>>>(pxz0, pxz1, U2f, U2b, out,
                                             out + (size_t)Bsz * Tt * 1024,
                                             nullptr, nullptr, 1);
}